// round 3
// baseline (speedup 1.0000x reference)
#include <cuda_runtime.h>

#define NB 8
#define NC 512
#define NN 4096
#define ND 64
#define NT 128
#define EPSF 1e-10f

// Scratch (allocation-free): per-batch K-moment matrices.
__device__ float g_KX[NB * ND * NC];    // KX[b][d][e] = sum_n Kf[d,n] * x[e,n]
__device__ float g_Ksum[NB * ND];       // Ksum[b][d]  = sum_n Kf[d,n]
__device__ float g_KV[NB * ND * NC];    // KV[b][d][c] = KX.wv^T + bv*Ksum

__device__ __forceinline__ float delu(float v) {
    return 10.0f * fmaxf(v, 0.0f) + __expf(10.0f * fminf(v, 0.0f));
}

__global__ void k_zero() {
    int i = blockIdx.x * blockDim.x + threadIdx.x;
    int stride = gridDim.x * blockDim.x;
    for (int j = i; j < NB * ND * NC; j += stride) g_KX[j] = 0.0f;
    if (i < NB * ND) g_Ksum[i] = 0.0f;
}

// ---------------------------------------------------------------------------
// K1: per (batch, 128-pixel tile):
//   phase A: K[64][128] = wk[64,512] @ x[512, tile]; kf = delu(K + bk); Ksum partials
//   phase B: KX[64][512] += kf @ x_tile^T   (atomic accumulate)
// Dynamic smem: xs[64][129] | kf[64][129] | wks[64][65] | ksum_s[64]
// ---------------------------------------------------------------------------
__global__ void __launch_bounds__(256) k1_kproj_kx(
    const float* __restrict__ x, const float* __restrict__ wk,
    const float* __restrict__ bk)
{
    extern __shared__ float sm[];
    float* xs     = sm;          // 8256 floats
    float* kf     = sm + 8256;   // 8256 floats
    float* wks    = sm + 16512;  // 4160 floats, [k][d] transposed
    float* ksum_s = sm + 20672;  // 64 floats

    const int tid = threadIdx.x;
    const int tx = tid & 15, ty = tid >> 4;
    const int b = blockIdx.y;
    const int n0 = blockIdx.x * NT;
    const float* xb = x + (size_t)b * NC * NN;

    if (tid < ND) ksum_s[tid] = 0.0f;

    float acc[4][8];
#pragma unroll
    for (int r = 0; r < 4; r++)
#pragma unroll
        for (int i = 0; i < 8; i++) acc[r][i] = 0.0f;

    // ---- phase A: K projection ----
    for (int ck = 0; ck < NC / 64; ck++) {
        __syncthreads();
#pragma unroll
        for (int it = 0; it < 8; it++) {
            int f4 = tid + it * 256;
            int row = f4 >> 5;           // 32 float4 per 128-wide row
            int c4 = f4 & 31;
            float4 v = *reinterpret_cast<const float4*>(
                xb + (size_t)(ck * 64 + row) * NN + n0 + c4 * 4);
            float* d = xs + row * 129 + c4 * 4;
            d[0] = v.x; d[1] = v.y; d[2] = v.z; d[3] = v.w;
        }
#pragma unroll
        for (int it = 0; it < 16; it++) {
            int idx = tid + it * 256;
            int dd = idx >> 6;
            int kk = idx & 63;
            wks[kk * 65 + dd] = wk[dd * NC + ck * 64 + kk];
        }
        __syncthreads();
#pragma unroll 4
        for (int k = 0; k < 64; k++) {
            float a0 = wks[k * 65 + ty * 4 + 0];
            float a1 = wks[k * 65 + ty * 4 + 1];
            float a2 = wks[k * 65 + ty * 4 + 2];
            float a3 = wks[k * 65 + ty * 4 + 3];
            float bb[8];
#pragma unroll
            for (int i = 0; i < 8; i++) bb[i] = xs[k * 129 + tx + 16 * i];
#pragma unroll
            for (int i = 0; i < 8; i++) {
                acc[0][i] += a0 * bb[i];
                acc[1][i] += a1 * bb[i];
                acc[2][i] += a2 * bb[i];
                acc[3][i] += a3 * bb[i];
            }
        }
    }

    // delu + kf store + Ksum partials
#pragma unroll
    for (int r = 0; r < 4; r++) {
        int dd = ty * 4 + r;
        float bkv = bk[dd];
        float part = 0.0f;
#pragma unroll
        for (int i = 0; i < 8; i++) {
            float v = delu(acc[r][i] + bkv);
            kf[dd * 129 + tx + 16 * i] = v;
            part += v;
        }
        atomicAdd(&ksum_s[dd], part);
    }
    __syncthreads();
    if (tid < ND) atomicAdd(&g_Ksum[b * ND + tid], ksum_s[tid]);

    // ---- phase B: KX accumulation ----
    for (int ec = 0; ec < NC / 64; ec++) {
        __syncthreads();
#pragma unroll
        for (int it = 0; it < 8; it++) {
            int f4 = tid + it * 256;
            int row = f4 >> 5;
            int c4 = f4 & 31;
            float4 v = *reinterpret_cast<const float4*>(
                xb + (size_t)(ec * 64 + row) * NN + n0 + c4 * 4);
            float* d = xs + row * 129 + c4 * 4;
            d[0] = v.x; d[1] = v.y; d[2] = v.z; d[3] = v.w;
        }
        __syncthreads();
        float accB[4][4];
#pragma unroll
        for (int r = 0; r < 4; r++)
#pragma unroll
            for (int i = 0; i < 4; i++) accB[r][i] = 0.0f;
#pragma unroll 4
        for (int j = 0; j < NT; j++) {
            float a0 = kf[(ty * 4 + 0) * 129 + j];
            float a1 = kf[(ty * 4 + 1) * 129 + j];
            float a2 = kf[(ty * 4 + 2) * 129 + j];
            float a3 = kf[(ty * 4 + 3) * 129 + j];
            float bb[4];
#pragma unroll
            for (int i = 0; i < 4; i++) bb[i] = xs[(tx + 16 * i) * 129 + j];
#pragma unroll
            for (int i = 0; i < 4; i++) {
                accB[0][i] += a0 * bb[i];
                accB[1][i] += a1 * bb[i];
                accB[2][i] += a2 * bb[i];
                accB[3][i] += a3 * bb[i];
            }
        }
#pragma unroll
        for (int r = 0; r < 4; r++)
#pragma unroll
            for (int i = 0; i < 4; i++)
                atomicAdd(&g_KX[((size_t)b * ND + ty * 4 + r) * NC + ec * 64 + tx + 16 * i],
                          accB[r][i]);
    }
}

// ---------------------------------------------------------------------------
// K2: KV[b][d][c] = sum_e KX[b][d][e]*wv[c][e] + bv[c]*Ksum[b][d]   (tiny GEMM)
// ---------------------------------------------------------------------------
__global__ void __launch_bounds__(256) k2_kv(
    const float* __restrict__ wv, const float* __restrict__ bv)
{
    __shared__ float wvs[64 * 65];
    __shared__ float kxs[64 * 65];
    __shared__ float ksm[64];
    const int tid = threadIdx.x;
    const int tx = tid & 15, ty = tid >> 4;
    const int b = blockIdx.y;
    const int c0 = blockIdx.x * 64;

    if (tid < 64) ksm[tid] = g_Ksum[b * 64 + tid];

    float acc[4][4];
#pragma unroll
    for (int r = 0; r < 4; r++)
#pragma unroll
        for (int i = 0; i < 4; i++) acc[r][i] = 0.0f;

    for (int ec = 0; ec < 8; ec++) {
        __syncthreads();
#pragma unroll
        for (int it = 0; it < 16; it++) {
            int idx = tid + it * 256;
            int row = idx >> 6;
            int e = idx & 63;
            wvs[row * 65 + e] = wv[(size_t)(c0 + row) * NC + ec * 64 + e];
            kxs[row * 65 + e] = g_KX[((size_t)b * ND + row) * NC + ec * 64 + e];
        }
        __syncthreads();
#pragma unroll 4
        for (int k = 0; k < 64; k++) {
            float a0 = kxs[(ty * 4 + 0) * 65 + k];
            float a1 = kxs[(ty * 4 + 1) * 65 + k];
            float a2 = kxs[(ty * 4 + 2) * 65 + k];
            float a3 = kxs[(ty * 4 + 3) * 65 + k];
            float bb[4];
#pragma unroll
            for (int i = 0; i < 4; i++) bb[i] = wvs[(tx + 16 * i) * 65 + k];
#pragma unroll
            for (int i = 0; i < 4; i++) {
                acc[0][i] += a0 * bb[i];
                acc[1][i] += a1 * bb[i];
                acc[2][i] += a2 * bb[i];
                acc[3][i] += a3 * bb[i];
            }
        }
    }
#pragma unroll
    for (int r = 0; r < 4; r++) {
        int dd = ty * 4 + r;
        float ks = ksm[dd];
#pragma unroll
        for (int i = 0; i < 4; i++) {
            int c = c0 + tx + 16 * i;
            g_KV[((size_t)b * ND + dd) * NC + c] = acc[r][i] + bv[c] * ks;
        }
    }
}

// ---------------------------------------------------------------------------
// K3: per (batch, tile):
//   Q = wq @ x_tile; qf = delu(Q + bq)
//   norm[j] = 1 / sum_d qf[d][j]*(Ksum[d]+eps)
//   out[c][j] = x[c][j] + gamma*norm[j]* sum_d qf[d][j]*KV[d][c]
// Dynamic smem: xs[64][129] | qf[64][129] | wqs/kvs[64][65] | ksums[64] | norm[128]
// ---------------------------------------------------------------------------
__global__ void __launch_bounds__(256) k3_out(
    const float* __restrict__ x, const float* __restrict__ wq,
    const float* __restrict__ bq, const float* __restrict__ gamma,
    float* __restrict__ out)
{
    extern __shared__ float sm[];
    float* xs     = sm;          // 8256
    float* qf     = sm + 8256;   // 8256
    float* wqs    = sm + 16512;  // 4160 (reused as kvs in phase C)
    float* ksums  = sm + 20672;  // 64
    float* norm_s = sm + 20736;  // 128

    const int tid = threadIdx.x;
    const int tx = tid & 15, ty = tid >> 4;
    const int b = blockIdx.y;
    const int n0 = blockIdx.x * NT;
    const float* xb = x + (size_t)b * NC * NN;

    if (tid < ND) ksums[tid] = g_Ksum[b * ND + tid] + EPSF;

    float acc[4][8];
#pragma unroll
    for (int r = 0; r < 4; r++)
#pragma unroll
        for (int i = 0; i < 8; i++) acc[r][i] = 0.0f;

    // ---- phase A: Q projection ----
    for (int ck = 0; ck < NC / 64; ck++) {
        __syncthreads();
#pragma unroll
        for (int it = 0; it < 8; it++) {
            int f4 = tid + it * 256;
            int row = f4 >> 5;
            int c4 = f4 & 31;
            float4 v = *reinterpret_cast<const float4*>(
                xb + (size_t)(ck * 64 + row) * NN + n0 + c4 * 4);
            float* d = xs + row * 129 + c4 * 4;
            d[0] = v.x; d[1] = v.y; d[2] = v.z; d[3] = v.w;
        }
#pragma unroll
        for (int it = 0; it < 16; it++) {
            int idx = tid + it * 256;
            int dd = idx >> 6;
            int kk = idx & 63;
            wqs[kk * 65 + dd] = wq[dd * NC + ck * 64 + kk];
        }
        __syncthreads();
#pragma unroll 4
        for (int k = 0; k < 64; k++) {
            float a0 = wqs[k * 65 + ty * 4 + 0];
            float a1 = wqs[k * 65 + ty * 4 + 1];
            float a2 = wqs[k * 65 + ty * 4 + 2];
            float a3 = wqs[k * 65 + ty * 4 + 3];
            float bb[8];
#pragma unroll
            for (int i = 0; i < 8; i++) bb[i] = xs[k * 129 + tx + 16 * i];
#pragma unroll
            for (int i = 0; i < 8; i++) {
                acc[0][i] += a0 * bb[i];
                acc[1][i] += a1 * bb[i];
                acc[2][i] += a2 * bb[i];
                acc[3][i] += a3 * bb[i];
            }
        }
    }
#pragma unroll
    for (int r = 0; r < 4; r++) {
        int dd = ty * 4 + r;
        float bqv = bq[dd];
#pragma unroll
        for (int i = 0; i < 8; i++)
            qf[dd * 129 + tx + 16 * i] = delu(acc[r][i] + bqv);
    }
    __syncthreads();

    // ---- norm ----
    if (tid < NT) {
        float s = 0.0f;
#pragma unroll 8
        for (int d = 0; d < ND; d++) s += qf[d * 129 + tid] * ksums[d];
        norm_s[tid] = 1.0f / s;
    }

    const float gam = gamma[0];
    float* kvs = wqs;  // alias: wq tiles no longer needed

    // ---- phase C: attn + residual ----
    for (int cc = 0; cc < NC / 64; cc++) {
        __syncthreads();
#pragma unroll
        for (int it = 0; it < 16; it++) {
            int idx = tid + it * 256;
            int dd = idx >> 6;
            int e = idx & 63;
            kvs[dd * 65 + e] = g_KV[((size_t)b * ND + dd) * NC + cc * 64 + e];
        }
        __syncthreads();
        float acc2[4][8];
#pragma unroll
        for (int r = 0; r < 4; r++)
#pragma unroll
            for (int i = 0; i < 8; i++) acc2[r][i] = 0.0f;
#pragma unroll 4
        for (int k = 0; k < 64; k++) {
            float a0 = kvs[k * 65 + ty * 4 + 0];
            float a1 = kvs[k * 65 + ty * 4 + 1];
            float a2 = kvs[k * 65 + ty * 4 + 2];
            float a3 = kvs[k * 65 + ty * 4 + 3];
            float bb[8];
#pragma unroll
            for (int i = 0; i < 8; i++) bb[i] = qf[k * 129 + tx + 16 * i];
#pragma unroll
            for (int i = 0; i < 8; i++) {
                acc2[0][i] += a0 * bb[i];
                acc2[1][i] += a1 * bb[i];
                acc2[2][i] += a2 * bb[i];
                acc2[3][i] += a3 * bb[i];
            }
        }
#pragma unroll
        for (int r = 0; r < 4; r++) {
#pragma unroll
            for (int i = 0; i < 8; i++) {
                int c = cc * 64 + ty * 4 + r;
                int j = tx + 16 * i;
                size_t off = ((size_t)b * NC + c) * NN + n0 + j;
                out[off] = x[off] + gam * norm_s[j] * acc2[r][i];
            }
        }
    }
}

extern "C" void kernel_launch(void* const* d_in, const int* in_sizes, int n_in,
                              void* d_out, int out_size)
{
    (void)in_sizes; (void)n_in; (void)out_size;
    const float* x     = (const float*)d_in[0];
    const float* wq    = (const float*)d_in[1];
    const float* bq    = (const float*)d_in[2];
    const float* wk    = (const float*)d_in[3];
    const float* bk    = (const float*)d_in[4];
    const float* wv    = (const float*)d_in[5];
    const float* bv    = (const float*)d_in[6];
    const float* gamma = (const float*)d_in[7];
    float* out = (float*)d_out;

    cudaFuncSetAttribute(k1_kproj_kx, cudaFuncAttributeMaxDynamicSharedMemorySize, 20736 * 4);
    cudaFuncSetAttribute(k3_out,      cudaFuncAttributeMaxDynamicSharedMemorySize, 20864 * 4);

    k_zero<<<256, 256>>>();
    k1_kproj_kx<<<dim3(NN / NT, NB), 256, 20736 * 4>>>(x, wk, bk);
    k2_kv<<<dim3(NC / 64, NB), 256>>>(wv, bv);
    k3_out<<<dim3(NN / NT, NB), 256, 20864 * 4>>>(x, wq, bq, gamma, out);
}

// round 6
// speedup vs baseline: 1.1318x; 1.1318x over previous
#include <cuda_runtime.h>
#include <cuda_bf16.h>
#include <mma.h>
#include <cstdint>

using namespace nvcuda;

#define NB 8
#define NC 512
#define NN 4096
#define ND 64
#define EPSF 1e-10f

// ---------------- scratch (allocation-free) ----------------
__device__ __nv_bfloat16 g_qf_hi[(size_t)NB * NN * ND];  // [b][pix][d]
__device__ __nv_bfloat16 g_qf_lo[(size_t)NB * NN * ND];
__device__ __nv_bfloat16 g_kf_hi[(size_t)NB * ND * NN];  // [b][d][pix]
__device__ __nv_bfloat16 g_kf_lo[(size_t)NB * ND * NN];
__device__ float g_KXT[(size_t)NB * NC * ND];            // [b][c][d]
__device__ float g_KVT[(size_t)NB * NC * ND];            // [b][c][d]
__device__ float g_Ksum[NB * ND];

__device__ __forceinline__ float delu(float v) {
    return 10.0f * fmaxf(v, 0.0f) + __expf(10.0f * fminf(v, 0.0f));
}
__device__ __forceinline__ void split_bf16(float v, __nv_bfloat16& h, __nv_bfloat16& l) {
    h = __float2bfloat16(v);
    l = __float2bfloat16(v - __bfloat162float(h));
}

__global__ void k_zero() {
    int i = blockIdx.x * blockDim.x + threadIdx.x;
    int stride = gridDim.x * blockDim.x;
    for (size_t j = i; j < (size_t)NB * NC * ND; j += stride) g_KXT[j] = 0.0f;
    if (i < NB * ND) g_Ksum[i] = 0.0f;
}

typedef wmma::fragment<wmma::matrix_a, 16, 16, 16, __nv_bfloat16, wmma::col_major> FragAc;
typedef wmma::fragment<wmma::matrix_a, 16, 16, 16, __nv_bfloat16, wmma::row_major> FragAr;
typedef wmma::fragment<wmma::matrix_b, 16, 16, 16, __nv_bfloat16, wmma::row_major> FragBr;
typedef wmma::fragment<wmma::matrix_b, 16, 16, 16, __nv_bfloat16, wmma::col_major> FragBc;
typedef wmma::fragment<wmma::accumulator, 16, 16, 16, float> FragC;

// ---------------------------------------------------------------------------
// kA: per (b, 128-pixel tile): D[p][n] = sum_c x[c][p] * W[n][c], n<64:Q, n>=64:K
//   wmma bf16 hi/lo (AhBh+AhBl+AlBh), fp32 accum. Epilogue: delu -> scratch.
// smem: bq[64]f | bk[64]f | ksum[64]f | stage(As hi/lo [64][136], Bs hi/lo [64][136])
//       Cs f32[128][132] aliases stage.
// ---------------------------------------------------------------------------
#define A_BQ   0
#define A_BK   256
#define A_KS   512
#define A_STG  768
#define A_AH   (A_STG)
#define A_AL   (A_STG + 17408)
#define A_BH   (A_STG + 34816)
#define A_BL   (A_STG + 52224)
#define A_TOT  (A_STG + 69632)
#define A_LDA  136
#define A_LDC  132

__global__ void __launch_bounds__(256) kA_proj(
    const float* __restrict__ x, const float* __restrict__ wq,
    const float* __restrict__ bq, const float* __restrict__ wk,
    const float* __restrict__ bk)
{
    extern __shared__ char smem[];
    float* s_bq = (float*)(smem + A_BQ);
    float* s_bk = (float*)(smem + A_BK);
    float* s_ks = (float*)(smem + A_KS);
    __nv_bfloat16* As_hi = (__nv_bfloat16*)(smem + A_AH);
    __nv_bfloat16* As_lo = (__nv_bfloat16*)(smem + A_AL);
    __nv_bfloat16* Bs_hi = (__nv_bfloat16*)(smem + A_BH);
    __nv_bfloat16* Bs_lo = (__nv_bfloat16*)(smem + A_BL);
    float* Cs = (float*)(smem + A_STG);

    const int tid = threadIdx.x, wid = tid >> 5, lane = tid & 31;
    const int b = blockIdx.y, n0 = blockIdx.x * 128;
    const float* xb = x + (size_t)b * NC * NN;

    if (tid < 64) { s_bq[tid] = bq[tid]; s_bk[tid] = bk[tid]; s_ks[tid] = 0.0f; }

    const int m0 = (wid & 3) * 32;        // pixel rows
    const int nw0 = (wid >> 2) * 64;      // output cols (Q/K halves)

    FragC acc[2][4];
#pragma unroll
    for (int mi = 0; mi < 2; mi++)
#pragma unroll
        for (int ni = 0; ni < 4; ni++) wmma::fill_fragment(acc[mi][ni], 0.0f);

    for (int ck = 0; ck < 8; ck++) {
        const int c0 = ck * 64;
        __syncthreads();
        // As[k=cc][m=p] (col_major A), coalesced reads, stride-1 writes
#pragma unroll
        for (int i = 0; i < 32; i++) {
            int idx = tid + i * 256;
            int p = idx & 127, cc = idx >> 7;
            float v = xb[(size_t)(c0 + cc) * NN + n0 + p];
            __nv_bfloat16 h, l; split_bf16(v, h, l);
            As_hi[cc * A_LDA + p] = h;
            As_lo[cc * A_LDA + p] = l;
        }
        // Bs[k=cc][n] (row_major B), n<64 -> wq, n>=64 -> wk
#pragma unroll
        for (int i = 0; i < 32; i++) {
            int idx = tid + i * 256;
            int cc = idx & 63, n = idx >> 6;
            float v = (n < 64) ? wq[n * NC + c0 + cc] : wk[(n - 64) * NC + c0 + cc];
            __nv_bfloat16 h, l; split_bf16(v, h, l);
            Bs_hi[cc * A_LDA + n] = h;
            Bs_lo[cc * A_LDA + n] = l;
        }
        __syncthreads();
#pragma unroll
        for (int s = 0; s < 4; s++) {
            FragAc ah[2], al[2];
            FragBr bh[4], bl[4];
#pragma unroll
            for (int mi = 0; mi < 2; mi++) {
                wmma::load_matrix_sync(ah[mi], As_hi + s * 16 * A_LDA + m0 + mi * 16, A_LDA);
                wmma::load_matrix_sync(al[mi], As_lo + s * 16 * A_LDA + m0 + mi * 16, A_LDA);
            }
#pragma unroll
            for (int ni = 0; ni < 4; ni++) {
                wmma::load_matrix_sync(bh[ni], Bs_hi + s * 16 * A_LDA + nw0 + ni * 16, A_LDA);
                wmma::load_matrix_sync(bl[ni], Bs_lo + s * 16 * A_LDA + nw0 + ni * 16, A_LDA);
            }
#pragma unroll
            for (int mi = 0; mi < 2; mi++)
#pragma unroll
                for (int ni = 0; ni < 4; ni++) {
                    wmma::mma_sync(acc[mi][ni], ah[mi], bh[ni], acc[mi][ni]);
                    wmma::mma_sync(acc[mi][ni], ah[mi], bl[ni], acc[mi][ni]);
                    wmma::mma_sync(acc[mi][ni], al[mi], bh[ni], acc[mi][ni]);
                }
        }
    }
    __syncthreads();
#pragma unroll
    for (int mi = 0; mi < 2; mi++)
#pragma unroll
        for (int ni = 0; ni < 4; ni++)
            wmma::store_matrix_sync(Cs + (m0 + mi * 16) * A_LDC + nw0 + ni * 16,
                                    acc[mi][ni], A_LDC, wmma::mem_row_major);
    __syncthreads();

    // Q epilogue: qf[b][pix][d] bf16 hi/lo (coalesced d-pairs)
#pragma unroll
    for (int i = 0; i < 16; i++) {
        int idx = tid + i * 256;
        int dp = idx & 31, p = idx >> 5;
        float f0 = delu(Cs[p * A_LDC + dp * 2] + s_bq[dp * 2]);
        float f1 = delu(Cs[p * A_LDC + dp * 2 + 1] + s_bq[dp * 2 + 1]);
        __nv_bfloat16 h0, l0, h1, l1;
        split_bf16(f0, h0, l0); split_bf16(f1, h1, l1);
        size_t qb = ((size_t)b * NN + n0 + p) * ND + dp * 2;
        *reinterpret_cast<__nv_bfloat162*>(g_qf_hi + qb) = __halves2bfloat162(h0, h1);
        *reinterpret_cast<__nv_bfloat162*>(g_qf_lo + qb) = __halves2bfloat162(l0, l1);
    }
    // K epilogue: kf[b][d][pix] + Ksum (warp = 32 consecutive pixels, same d)
#pragma unroll
    for (int i = 0; i < 32; i++) {
        int idx = tid + i * 256;
        int p = idx & 127, d = idx >> 7;
        float f = delu(Cs[p * A_LDC + 64 + d] + s_bk[d]);
        __nv_bfloat16 h, l; split_bf16(f, h, l);
        size_t kb = ((size_t)b * ND + d) * NN + n0 + p;
        g_kf_hi[kb] = h;
        g_kf_lo[kb] = l;
        float s = f;
#pragma unroll
        for (int o = 16; o > 0; o >>= 1) s += __shfl_xor_sync(0xffffffffu, s, o);
        if (lane == 0) atomicAdd(&s_ks[d], s);
    }
    __syncthreads();
    if (tid < 64) atomicAdd(&g_Ksum[b * ND + tid], s_ks[tid]);
}

// ---------------------------------------------------------------------------
// kB: KXT[c][d] += sum_n x[c][n]*kf[d][n]  (c-block 128, pixel-range 1024, z=4)
// smem: As hi/lo [128][72] (row_major A), Bs hi/lo [64][72] (col_major B),
//       Cs f32[128][68] aliases.
// ---------------------------------------------------------------------------
#define B_AH   0
#define B_AL   18432
#define B_BH   36864
#define B_BL   46080
#define B_TOT  55296
#define B_LD   72
#define B_LDC  68

__global__ void __launch_bounds__(256) kB_kx(const float* __restrict__ x)
{
    extern __shared__ char smem[];
    __nv_bfloat16* As_hi = (__nv_bfloat16*)(smem + B_AH);
    __nv_bfloat16* As_lo = (__nv_bfloat16*)(smem + B_AL);
    __nv_bfloat16* Bs_hi = (__nv_bfloat16*)(smem + B_BH);
    __nv_bfloat16* Bs_lo = (__nv_bfloat16*)(smem + B_BL);
    float* Cs = (float*)(smem + 0);

    const int tid = threadIdx.x, wid = tid >> 5;
    const int cblk = blockIdx.x, b = blockIdx.y, p0 = blockIdx.z * 1024;
    const float* xb = x + (size_t)b * NC * NN;

    const int m0 = (wid & 3) * 32;     // c rows
    const int nw0 = (wid >> 2) * 32;   // d cols

    FragC acc[2][2];
#pragma unroll
    for (int mi = 0; mi < 2; mi++)
#pragma unroll
        for (int ni = 0; ni < 2; ni++) wmma::fill_fragment(acc[mi][ni], 0.0f);

    for (int ch = 0; ch < 16; ch++) {
        const int pc = p0 + ch * 64;
        __syncthreads();
        // As[m=c][k=j]
#pragma unroll
        for (int i = 0; i < 32; i++) {
            int idx = tid + i * 256;
            int j = idx & 63, c = idx >> 6;
            float v = xb[(size_t)(cblk * 128 + c) * NN + pc + j];
            __nv_bfloat16 h, l; split_bf16(v, h, l);
            As_hi[c * B_LD + j] = h;
            As_lo[c * B_LD + j] = l;
        }
        // Bs[n=d][k=j] (col_major B: element (k,n) at n*ld + k)
#pragma unroll
        for (int i = 0; i < 8; i++) {
            int idx = tid + i * 256;
            int jp = idx & 31, d = idx >> 5;
            size_t base = ((size_t)b * ND + d) * NN + pc + jp * 2;
            uint32_t hh = *reinterpret_cast<const uint32_t*>(g_kf_hi + base);
            uint32_t ll = *reinterpret_cast<const uint32_t*>(g_kf_lo + base);
            *reinterpret_cast<uint32_t*>(&Bs_hi[d * B_LD + jp * 2]) = hh;
            *reinterpret_cast<uint32_t*>(&Bs_lo[d * B_LD + jp * 2]) = ll;
        }
        __syncthreads();
#pragma unroll
        for (int s = 0; s < 4; s++) {
            FragAr ah[2], al[2];
            FragBc bh[2], bl[2];
#pragma unroll
            for (int mi = 0; mi < 2; mi++) {
                wmma::load_matrix_sync(ah[mi], As_hi + (m0 + mi * 16) * B_LD + s * 16, B_LD);
                wmma::load_matrix_sync(al[mi], As_lo + (m0 + mi * 16) * B_LD + s * 16, B_LD);
            }
#pragma unroll
            for (int ni = 0; ni < 2; ni++) {
                wmma::load_matrix_sync(bh[ni], Bs_hi + (nw0 + ni * 16) * B_LD + s * 16, B_LD);
                wmma::load_matrix_sync(bl[ni], Bs_lo + (nw0 + ni * 16) * B_LD + s * 16, B_LD);
            }
#pragma unroll
            for (int mi = 0; mi < 2; mi++)
#pragma unroll
                for (int ni = 0; ni < 2; ni++) {
                    wmma::mma_sync(acc[mi][ni], ah[mi], bh[ni], acc[mi][ni]);
                    wmma::mma_sync(acc[mi][ni], ah[mi], bl[ni], acc[mi][ni]);
                    wmma::mma_sync(acc[mi][ni], al[mi], bh[ni], acc[mi][ni]);
                }
        }
    }
    __syncthreads();
#pragma unroll
    for (int mi = 0; mi < 2; mi++)
#pragma unroll
        for (int ni = 0; ni < 2; ni++)
            wmma::store_matrix_sync(Cs + (m0 + mi * 16) * B_LDC + nw0 + ni * 16,
                                    acc[mi][ni], B_LDC, wmma::mem_row_major);
    __syncthreads();
#pragma unroll
    for (int i = 0; i < 32; i++) {
        int idx = tid + i * 256;
        int d = idx & 63, c = idx >> 6;
        atomicAdd(&g_KXT[((size_t)b * NC + cblk * 128 + c) * ND + d], Cs[c * B_LDC + d]);
    }
}

// ---------------------------------------------------------------------------
// k2: KVT[b][c'][d] = sum_c wv[c'][c]*KXT[b][c][d] + bv[c']*Ksum[b][d]  (SIMT)
// ---------------------------------------------------------------------------
__global__ void __launch_bounds__(256) k2_kv(
    const float* __restrict__ wv, const float* __restrict__ bv)
{
    __shared__ float wvs[64 * 65];   // [c'][c]
    __shared__ float kxs[64 * 65];   // [c][d]
    __shared__ float ksm[64];
    const int tid = threadIdx.x;
    const int tx = tid & 15, ty = tid >> 4;
    const int b = blockIdx.y;
    const int c0 = blockIdx.x * 64;

    if (tid < 64) ksm[tid] = g_Ksum[b * 64 + tid];

    float acc[4][4];
#pragma unroll
    for (int r = 0; r < 4; r++)
#pragma unroll
        for (int i = 0; i < 4; i++) acc[r][i] = 0.0f;

    for (int cc = 0; cc < 8; cc++) {
        __syncthreads();
#pragma unroll
        for (int it = 0; it < 16; it++) {
            int idx = tid + it * 256;
            int k = idx & 63, row = idx >> 6;
            wvs[row * 65 + k] = wv[(size_t)(c0 + row) * NC + cc * 64 + k];
            kxs[row * 65 + k] = g_KXT[((size_t)b * NC + cc * 64 + row) * ND + k];
        }
        __syncthreads();
#pragma unroll 4
        for (int k = 0; k < 64; k++) {
            float a0 = wvs[(ty * 4 + 0) * 65 + k];
            float a1 = wvs[(ty * 4 + 1) * 65 + k];
            float a2 = wvs[(ty * 4 + 2) * 65 + k];
            float a3 = wvs[(ty * 4 + 3) * 65 + k];
            float bb[4];
#pragma unroll
            for (int i = 0; i < 4; i++) bb[i] = kxs[k * 65 + tx + 16 * i];
#pragma unroll
            for (int i = 0; i < 4; i++) {
                acc[0][i] += a0 * bb[i];
                acc[1][i] += a1 * bb[i];
                acc[2][i] += a2 * bb[i];
                acc[3][i] += a3 * bb[i];
            }
        }
    }
#pragma unroll
    for (int r = 0; r < 4; r++) {
        int cp = c0 + ty * 4 + r;
        float bvv = bv[cp];
#pragma unroll
        for (int i = 0; i < 4; i++) {
            int d = tx + 16 * i;
            g_KVT[((size_t)b * NC + cp) * ND + d] = acc[r][i] + bvv * ksm[d];
        }
    }
}

// ---------------------------------------------------------------------------
// kD: D[p][c] = sum_d qf[p][d]*KVT[c][d]; out = x + gamma*norm[p]*D
// smem: ksum[64]f | norm[128]f | As hi/lo [128][72] | Bs hi/lo [64][72] |
//       Cs f32[128][68] (separate; As persists)
// ---------------------------------------------------------------------------
#define D_KS   0
#define D_NORM 256
#define D_AH   768
#define D_AL   (768 + 18432)
#define D_BH   (768 + 36864)
#define D_BL   (768 + 46080)
#define D_CS   (768 + 55296)
#define D_TOT  (768 + 55296 + 34816)
#define D_LD   72
#define D_LDC  68

__global__ void __launch_bounds__(256) kD_out(
    const float* __restrict__ x, const float* __restrict__ gamma,
    float* __restrict__ out)
{
    extern __shared__ char smem[];
    float* s_ks = (float*)(smem + D_KS);
    float* s_nm = (float*)(smem + D_NORM);
    __nv_bfloat16* As_hi = (__nv_bfloat16*)(smem + D_AH);
    __nv_bfloat16* As_lo = (__nv_bfloat16*)(smem + D_AL);
    __nv_bfloat16* Bs_hi = (__nv_bfloat16*)(smem + D_BH);
    __nv_bfloat16* Bs_lo = (__nv_bfloat16*)(smem + D_BL);
    float* Cs = (float*)(smem + D_CS);

    const int tid = threadIdx.x, wid = tid >> 5;
    const int b = blockIdx.y, n0 = blockIdx.x * 128;

    if (tid < 64) s_ks[tid] = g_Ksum[b * 64 + tid] + EPSF;

    // As[m=p][k=d] from qf scratch (bf16, coalesced uint2)
#pragma unroll
    for (int i = 0; i < 8; i++) {
        int idx = tid + i * 256;
        int q4 = idx & 15, row = idx >> 4;
        size_t base = ((size_t)b * NN + n0 + row) * ND + q4 * 4;
        uint2 vh = *reinterpret_cast<const uint2*>(g_qf_hi + base);
        uint2 vl = *reinterpret_cast<const uint2*>(g_qf_lo + base);
        *reinterpret_cast<uint2*>(&As_hi[row * D_LD + q4 * 4]) = vh;
        *reinterpret_cast<uint2*>(&As_lo[row * D_LD + q4 * 4]) = vl;
    }
    __syncthreads();

    // per-pixel norm
    if (tid < 128) {
        float s = 0.0f;
#pragma unroll
        for (int dp = 0; dp < 32; dp++) {
            __nv_bfloat162 hh = *reinterpret_cast<__nv_bfloat162*>(&As_hi[tid * D_LD + dp * 2]);
            __nv_bfloat162 ll = *reinterpret_cast<__nv_bfloat162*>(&As_lo[tid * D_LD + dp * 2]);
            float f0 = __bfloat162float(__low2bfloat16(hh)) + __bfloat162float(__low2bfloat16(ll));
            float f1 = __bfloat162float(__high2bfloat16(hh)) + __bfloat162float(__high2bfloat16(ll));
            s += f0 * s_ks[dp * 2] + f1 * s_ks[dp * 2 + 1];
        }
        s_nm[tid] = gamma[0] / s;
    }

    const int m0 = (wid & 3) * 32;     // pixel rows
    const int nw0 = (wid >> 2) * 32;   // c cols within 64-chunk

    for (int cc = 0; cc < 8; cc++) {
        const int c0 = cc * 64;
        __syncthreads();   // prior-iter out-writes done; safe to restage Bs
        // Bs[n=c][k=d] (col_major B): KVT[c][d] fp32 -> bf16 hi/lo
#pragma unroll
        for (int i = 0; i < 8; i++) {
            int idx = tid + i * 256;
            int dp = idx & 31, row = idx >> 5;
            const float2 v = *reinterpret_cast<const float2*>(
                g_KVT + ((size_t)b * NC + c0 + row) * ND + dp * 2);
            __nv_bfloat16 h0, l0, h1, l1;
            split_bf16(v.x, h0, l0); split_bf16(v.y, h1, l1);
            *reinterpret_cast<__nv_bfloat162*>(&Bs_hi[row * D_LD + dp * 2]) = __halves2bfloat162(h0, h1);
            *reinterpret_cast<__nv_bfloat162*>(&Bs_lo[row * D_LD + dp * 2]) = __halves2bfloat162(l0, l1);
        }
        __syncthreads();

        FragC acc[2][2];
#pragma unroll
        for (int mi = 0; mi < 2; mi++)
#pragma unroll
            for (int ni = 0; ni < 2; ni++) wmma::fill_fragment(acc[mi][ni], 0.0f);

#pragma unroll
        for (int s = 0; s < 4; s++) {
            FragAr ah[2], al[2];
            FragBc bh[2], bl[2];
#pragma unroll
            for (int mi = 0; mi < 2; mi++) {
                wmma::load_matrix_sync(ah[mi], As_hi + (m0 + mi * 16) * D_LD + s * 16, D_LD);
                wmma::load_matrix_sync(al[mi], As_lo + (m0 + mi * 16) * D_LD + s * 16, D_LD);
            }
#pragma unroll
            for (int ni = 0; ni < 2; ni++) {
                wmma::load_matrix_sync(bh[ni], Bs_hi + (nw0 + ni * 16) * D_LD + s * 16, D_LD);
                wmma::load_matrix_sync(bl[ni], Bs_lo + (nw0 + ni * 16) * D_LD + s * 16, D_LD);
            }
#pragma unroll
            for (int mi = 0; mi < 2; mi++)
#pragma unroll
                for (int ni = 0; ni < 2; ni++) {
                    wmma::mma_sync(acc[mi][ni], ah[mi], bh[ni], acc[mi][ni]);
                    wmma::mma_sync(acc[mi][ni], ah[mi], bl[ni], acc[mi][ni]);
                    wmma::mma_sync(acc[mi][ni], al[mi], bh[ni], acc[mi][ni]);
                }
        }
#pragma unroll
        for (int mi = 0; mi < 2; mi++)
#pragma unroll
            for (int ni = 0; ni < 2; ni++)
                wmma::store_matrix_sync(Cs + (m0 + mi * 16) * D_LDC + nw0 + ni * 16,
                                        acc[mi][ni], D_LDC, wmma::mem_row_major);
        __syncthreads();
        // out = x + scale[p] * D  (coalesced in pixel)
#pragma unroll
        for (int i = 0; i < 32; i++) {
            int idx = tid + i * 256;
            int p = idx & 127, c = idx >> 7;  // c in 0..63
            size_t off = ((size_t)b * NC + c0 + c) * NN + n0 + p;
            out[off] = x[off] + s_nm[p] * Cs[p * D_LDC + c];
        }
    }
}

// ---------------------------------------------------------------------------
extern "C" void kernel_launch(void* const* d_in, const int* in_sizes, int n_in,
                              void* d_out, int out_size)
{
    (void)in_sizes; (void)n_in; (void)out_size;
    const float* x     = (const float*)d_in[0];
    const float* wq    = (const float*)d_in[1];
    const float* bq    = (const float*)d_in[2];
    const float* wk    = (const float*)d_in[3];
    const float* bk    = (const float*)d_in[4];
    const float* wv    = (const float*)d_in[5];
    const float* bv    = (const float*)d_in[6];
    const float* gamma = (const float*)d_in[7];
    float* out = (float*)d_out;

    cudaFuncSetAttribute(kA_proj, cudaFuncAttributeMaxDynamicSharedMemorySize, A_TOT);
    cudaFuncSetAttribute(kB_kx,   cudaFuncAttributeMaxDynamicSharedMemorySize, B_TOT);
    cudaFuncSetAttribute(kD_out,  cudaFuncAttributeMaxDynamicSharedMemorySize, D_TOT);

    k_zero<<<256, 256>>>();
    kA_proj<<<dim3(NN / 128, NB), 256, A_TOT>>>(x, wq, bq, wk, bk);
    kB_kx<<<dim3(4, NB, 4), 256, B_TOT>>>(x);
    k2_kv<<<dim3(NC / 64, NB), 256>>>(wv, bv);
    kD_out<<<dim3(NN / 128, NB), 256, D_TOT>>>(x, gamma, out);
}

// round 7
// speedup vs baseline: 1.5087x; 1.3329x over previous
#include <cuda_runtime.h>
#include <cuda_bf16.h>
#include <mma.h>
#include <cstdint>

using namespace nvcuda;

#define NB 8
#define NC 512
#define NN 4096
#define ND 64
#define EPSF 1e-10f

// ---------------- scratch (allocation-free) ----------------
__device__ __nv_bfloat16 g_qf_hi[(size_t)NB * NN * ND];  // [b][pix][d]
__device__ __nv_bfloat16 g_qf_lo[(size_t)NB * NN * ND];
__device__ __nv_bfloat16 g_kf_hi[(size_t)NB * ND * NN];  // [b][d][pix]
__device__ __nv_bfloat16 g_kf_lo[(size_t)NB * ND * NN];
__device__ float g_KXT[(size_t)NB * NC * ND];            // [b][c][d]
__device__ float g_KVT[(size_t)NB * NC * ND];            // [b][c][d]  (pure GEMM part)
__device__ float g_Ksum[NB * ND];

__device__ __forceinline__ float delu(float v) {
    return 10.0f * fmaxf(v, 0.0f) + __expf(10.0f * fminf(v, 0.0f));
}
__device__ __forceinline__ void split_bf16(float v, __nv_bfloat16& h, __nv_bfloat16& l) {
    h = __float2bfloat16(v);
    l = __float2bfloat16(v - __bfloat162float(h));
}

__global__ void k_zero() {
    int i = blockIdx.x * blockDim.x + threadIdx.x;
    int stride = gridDim.x * blockDim.x;
    for (size_t j = i; j < (size_t)NB * NC * ND; j += stride) {
        g_KXT[j] = 0.0f;
        g_KVT[j] = 0.0f;
    }
    if (i < NB * ND) g_Ksum[i] = 0.0f;
}

typedef wmma::fragment<wmma::matrix_a, 16, 16, 16, __nv_bfloat16, wmma::col_major> FragAc;
typedef wmma::fragment<wmma::matrix_a, 16, 16, 16, __nv_bfloat16, wmma::row_major> FragAr;
typedef wmma::fragment<wmma::matrix_b, 16, 16, 16, __nv_bfloat16, wmma::row_major> FragBr;
typedef wmma::fragment<wmma::matrix_b, 16, 16, 16, __nv_bfloat16, wmma::col_major> FragBc;
typedef wmma::fragment<wmma::accumulator, 16, 16, 16, float> FragC;

// ---------------------------------------------------------------------------
// kA: per (b, 128-pixel tile): D[p][n] = sum_c x[c][p] * W[n][c], n<64:Q, n>=64:K
// ---------------------------------------------------------------------------
#define A_BQ   0
#define A_BK   256
#define A_KS   512
#define A_STG  768
#define A_AH   (A_STG)
#define A_AL   (A_STG + 17408)
#define A_BH   (A_STG + 34816)
#define A_BL   (A_STG + 52224)
#define A_TOT  (A_STG + 69632)
#define A_LDA  136
#define A_LDC  132

__global__ void __launch_bounds__(256) kA_proj(
    const float* __restrict__ x, const float* __restrict__ wq,
    const float* __restrict__ bq, const float* __restrict__ wk,
    const float* __restrict__ bk)
{
    extern __shared__ char smem[];
    float* s_bq = (float*)(smem + A_BQ);
    float* s_bk = (float*)(smem + A_BK);
    float* s_ks = (float*)(smem + A_KS);
    __nv_bfloat16* As_hi = (__nv_bfloat16*)(smem + A_AH);
    __nv_bfloat16* As_lo = (__nv_bfloat16*)(smem + A_AL);
    __nv_bfloat16* Bs_hi = (__nv_bfloat16*)(smem + A_BH);
    __nv_bfloat16* Bs_lo = (__nv_bfloat16*)(smem + A_BL);
    float* Cs = (float*)(smem + A_STG);

    const int tid = threadIdx.x, wid = tid >> 5, lane = tid & 31;
    const int b = blockIdx.y, n0 = blockIdx.x * 128;
    const float* xb = x + (size_t)b * NC * NN;

    if (tid < 64) { s_bq[tid] = bq[tid]; s_bk[tid] = bk[tid]; s_ks[tid] = 0.0f; }

    const int m0 = (wid & 3) * 32;
    const int nw0 = (wid >> 2) * 64;

    FragC acc[2][4];
#pragma unroll
    for (int mi = 0; mi < 2; mi++)
#pragma unroll
        for (int ni = 0; ni < 4; ni++) wmma::fill_fragment(acc[mi][ni], 0.0f);

    for (int ck = 0; ck < 8; ck++) {
        const int c0 = ck * 64;
        __syncthreads();
#pragma unroll
        for (int i = 0; i < 32; i++) {
            int idx = tid + i * 256;
            int p = idx & 127, cc = idx >> 7;
            float v = xb[(size_t)(c0 + cc) * NN + n0 + p];
            __nv_bfloat16 h, l; split_bf16(v, h, l);
            As_hi[cc * A_LDA + p] = h;
            As_lo[cc * A_LDA + p] = l;
        }
#pragma unroll
        for (int i = 0; i < 32; i++) {
            int idx = tid + i * 256;
            int cc = idx & 63, n = idx >> 6;
            float v = (n < 64) ? wq[n * NC + c0 + cc] : wk[(n - 64) * NC + c0 + cc];
            __nv_bfloat16 h, l; split_bf16(v, h, l);
            Bs_hi[cc * A_LDA + n] = h;
            Bs_lo[cc * A_LDA + n] = l;
        }
        __syncthreads();
#pragma unroll
        for (int s = 0; s < 4; s++) {
            FragAc ah[2], al[2];
            FragBr bh[4], bl[4];
#pragma unroll
            for (int mi = 0; mi < 2; mi++) {
                wmma::load_matrix_sync(ah[mi], As_hi + s * 16 * A_LDA + m0 + mi * 16, A_LDA);
                wmma::load_matrix_sync(al[mi], As_lo + s * 16 * A_LDA + m0 + mi * 16, A_LDA);
            }
#pragma unroll
            for (int ni = 0; ni < 4; ni++) {
                wmma::load_matrix_sync(bh[ni], Bs_hi + s * 16 * A_LDA + nw0 + ni * 16, A_LDA);
                wmma::load_matrix_sync(bl[ni], Bs_lo + s * 16 * A_LDA + nw0 + ni * 16, A_LDA);
            }
#pragma unroll
            for (int mi = 0; mi < 2; mi++)
#pragma unroll
                for (int ni = 0; ni < 4; ni++) {
                    wmma::mma_sync(acc[mi][ni], ah[mi], bh[ni], acc[mi][ni]);
                    wmma::mma_sync(acc[mi][ni], ah[mi], bl[ni], acc[mi][ni]);
                    wmma::mma_sync(acc[mi][ni], al[mi], bh[ni], acc[mi][ni]);
                }
        }
    }
    __syncthreads();
#pragma unroll
    for (int mi = 0; mi < 2; mi++)
#pragma unroll
        for (int ni = 0; ni < 4; ni++)
            wmma::store_matrix_sync(Cs + (m0 + mi * 16) * A_LDC + nw0 + ni * 16,
                                    acc[mi][ni], A_LDC, wmma::mem_row_major);
    __syncthreads();

#pragma unroll
    for (int i = 0; i < 16; i++) {
        int idx = tid + i * 256;
        int dp = idx & 31, p = idx >> 5;
        float f0 = delu(Cs[p * A_LDC + dp * 2] + s_bq[dp * 2]);
        float f1 = delu(Cs[p * A_LDC + dp * 2 + 1] + s_bq[dp * 2 + 1]);
        __nv_bfloat16 h0, l0, h1, l1;
        split_bf16(f0, h0, l0); split_bf16(f1, h1, l1);
        size_t qb = ((size_t)b * NN + n0 + p) * ND + dp * 2;
        *reinterpret_cast<__nv_bfloat162*>(g_qf_hi + qb) = __halves2bfloat162(h0, h1);
        *reinterpret_cast<__nv_bfloat162*>(g_qf_lo + qb) = __halves2bfloat162(l0, l1);
    }
#pragma unroll
    for (int i = 0; i < 32; i++) {
        int idx = tid + i * 256;
        int p = idx & 127, d = idx >> 7;
        float f = delu(Cs[p * A_LDC + 64 + d] + s_bk[d]);
        __nv_bfloat16 h, l; split_bf16(f, h, l);
        size_t kb = ((size_t)b * ND + d) * NN + n0 + p;
        g_kf_hi[kb] = h;
        g_kf_lo[kb] = l;
        float s = f;
#pragma unroll
        for (int o = 16; o > 0; o >>= 1) s += __shfl_xor_sync(0xffffffffu, s, o);
        if (lane == 0) atomicAdd(&s_ks[d], s);
    }
    __syncthreads();
    if (tid < 64) atomicAdd(&g_Ksum[b * ND + tid], s_ks[tid]);
}

// ---------------------------------------------------------------------------
// kB: KXT[c][d] += sum_n x[c][n]*kf[d][n]  (c-block 128, pixel-range 1024, z=4)
// ---------------------------------------------------------------------------
#define B_AH   0
#define B_AL   18432
#define B_BH   36864
#define B_BL   46080
#define B_TOT  55296
#define B_LD   72
#define B_LDC  68

__global__ void __launch_bounds__(256) kB_kx(const float* __restrict__ x)
{
    extern __shared__ char smem[];
    __nv_bfloat16* As_hi = (__nv_bfloat16*)(smem + B_AH);
    __nv_bfloat16* As_lo = (__nv_bfloat16*)(smem + B_AL);
    __nv_bfloat16* Bs_hi = (__nv_bfloat16*)(smem + B_BH);
    __nv_bfloat16* Bs_lo = (__nv_bfloat16*)(smem + B_BL);
    float* Cs = (float*)(smem + 0);

    const int tid = threadIdx.x, wid = tid >> 5;
    const int cblk = blockIdx.x, b = blockIdx.y, p0 = blockIdx.z * 1024;
    const float* xb = x + (size_t)b * NC * NN;

    const int m0 = (wid & 3) * 32;
    const int nw0 = (wid >> 2) * 32;

    FragC acc[2][2];
#pragma unroll
    for (int mi = 0; mi < 2; mi++)
#pragma unroll
        for (int ni = 0; ni < 2; ni++) wmma::fill_fragment(acc[mi][ni], 0.0f);

    for (int ch = 0; ch < 16; ch++) {
        const int pc = p0 + ch * 64;
        __syncthreads();
#pragma unroll
        for (int i = 0; i < 32; i++) {
            int idx = tid + i * 256;
            int j = idx & 63, c = idx >> 6;
            float v = xb[(size_t)(cblk * 128 + c) * NN + pc + j];
            __nv_bfloat16 h, l; split_bf16(v, h, l);
            As_hi[c * B_LD + j] = h;
            As_lo[c * B_LD + j] = l;
        }
#pragma unroll
        for (int i = 0; i < 8; i++) {
            int idx = tid + i * 256;
            int jp = idx & 31, d = idx >> 5;
            size_t base = ((size_t)b * ND + d) * NN + pc + jp * 2;
            uint32_t hh = *reinterpret_cast<const uint32_t*>(g_kf_hi + base);
            uint32_t ll = *reinterpret_cast<const uint32_t*>(g_kf_lo + base);
            *reinterpret_cast<uint32_t*>(&Bs_hi[d * B_LD + jp * 2]) = hh;
            *reinterpret_cast<uint32_t*>(&Bs_lo[d * B_LD + jp * 2]) = ll;
        }
        __syncthreads();
#pragma unroll
        for (int s = 0; s < 4; s++) {
            FragAr ah[2], al[2];
            FragBc bh[2], bl[2];
#pragma unroll
            for (int mi = 0; mi < 2; mi++) {
                wmma::load_matrix_sync(ah[mi], As_hi + (m0 + mi * 16) * B_LD + s * 16, B_LD);
                wmma::load_matrix_sync(al[mi], As_lo + (m0 + mi * 16) * B_LD + s * 16, B_LD);
            }
#pragma unroll
            for (int ni = 0; ni < 2; ni++) {
                wmma::load_matrix_sync(bh[ni], Bs_hi + (nw0 + ni * 16) * B_LD + s * 16, B_LD);
                wmma::load_matrix_sync(bl[ni], Bs_lo + (nw0 + ni * 16) * B_LD + s * 16, B_LD);
            }
#pragma unroll
            for (int mi = 0; mi < 2; mi++)
#pragma unroll
                for (int ni = 0; ni < 2; ni++) {
                    wmma::mma_sync(acc[mi][ni], ah[mi], bh[ni], acc[mi][ni]);
                    wmma::mma_sync(acc[mi][ni], ah[mi], bl[ni], acc[mi][ni]);
                    wmma::mma_sync(acc[mi][ni], al[mi], bh[ni], acc[mi][ni]);
                }
        }
    }
    __syncthreads();
#pragma unroll
    for (int mi = 0; mi < 2; mi++)
#pragma unroll
        for (int ni = 0; ni < 2; ni++)
            wmma::store_matrix_sync(Cs + (m0 + mi * 16) * B_LDC + nw0 + ni * 16,
                                    acc[mi][ni], B_LDC, wmma::mem_row_major);
    __syncthreads();
#pragma unroll
    for (int i = 0; i < 32; i++) {
        int idx = tid + i * 256;
        int d = idx & 63, c = idx >> 6;
        atomicAdd(&g_KXT[((size_t)b * NC + cblk * 128 + c) * ND + d], Cs[c * B_LDC + d]);
    }
}

// ---------------------------------------------------------------------------
// k2 (wmma): KVT[c'][d] += sum_k wv[c'][k]*KXT[k][d], 4-way k-split, atomics.
// Bias term bv*Ksum is folded into kD analytically.
// grid (4 cblk, NB, 4 ksplit), 256 threads. smem layout identical to kB.
// ---------------------------------------------------------------------------
__global__ void __launch_bounds__(256) k2_kv(const float* __restrict__ wv)
{
    extern __shared__ char smem[];
    __nv_bfloat16* As_hi = (__nv_bfloat16*)(smem + B_AH);
    __nv_bfloat16* As_lo = (__nv_bfloat16*)(smem + B_AL);
    __nv_bfloat16* Bs_hi = (__nv_bfloat16*)(smem + B_BH);
    __nv_bfloat16* Bs_lo = (__nv_bfloat16*)(smem + B_BL);
    float* Cs = (float*)(smem + 0);

    const int tid = threadIdx.x, wid = tid >> 5;
    const int cblk = blockIdx.x, b = blockIdx.y, k0 = blockIdx.z * 128;

    const int m0 = (wid & 3) * 32;   // c' rows
    const int nw0 = (wid >> 2) * 32; // d cols

    FragC acc[2][2];
#pragma unroll
    for (int mi = 0; mi < 2; mi++)
#pragma unroll
        for (int ni = 0; ni < 2; ni++) wmma::fill_fragment(acc[mi][ni], 0.0f);

    for (int ch = 0; ch < 2; ch++) {
        const int kc = k0 + ch * 64;
        __syncthreads();
        // As[m=c'][k=j]: wv[c'][kc+j] fp32 -> hi/lo
#pragma unroll
        for (int i = 0; i < 32; i++) {
            int idx = tid + i * 256;
            int j = idx & 63, c = idx >> 6;
            float v = wv[(size_t)(cblk * 128 + c) * NC + kc + j];
            __nv_bfloat16 h, l; split_bf16(v, h, l);
            As_hi[c * B_LD + j] = h;
            As_lo[c * B_LD + j] = l;
        }
        // Bs[k=j][n=d] row-major B: KXT[kc+j][d] fp32 -> hi/lo
#pragma unroll
        for (int i = 0; i < 8; i++) {
            int idx = tid + i * 256;
            int dp = idx & 31, row = idx >> 5;
            const float2 v = *reinterpret_cast<const float2*>(
                g_KXT + ((size_t)b * NC + kc + row) * ND + dp * 2);
            __nv_bfloat16 h0, l0, h1, l1;
            split_bf16(v.x, h0, l0); split_bf16(v.y, h1, l1);
            *reinterpret_cast<__nv_bfloat162*>(&Bs_hi[row * B_LD + dp * 2]) = __halves2bfloat162(h0, h1);
            *reinterpret_cast<__nv_bfloat162*>(&Bs_lo[row * B_LD + dp * 2]) = __halves2bfloat162(l0, l1);
        }
        __syncthreads();
#pragma unroll
        for (int s = 0; s < 4; s++) {
            FragAr ah[2], al[2];
            FragBr bh[2], bl[2];
#pragma unroll
            for (int mi = 0; mi < 2; mi++) {
                wmma::load_matrix_sync(ah[mi], As_hi + (m0 + mi * 16) * B_LD + s * 16, B_LD);
                wmma::load_matrix_sync(al[mi], As_lo + (m0 + mi * 16) * B_LD + s * 16, B_LD);
            }
#pragma unroll
            for (int ni = 0; ni < 2; ni++) {
                wmma::load_matrix_sync(bh[ni], Bs_hi + s * 16 * B_LD + nw0 + ni * 16, B_LD);
                wmma::load_matrix_sync(bl[ni], Bs_lo + s * 16 * B_LD + nw0 + ni * 16, B_LD);
            }
#pragma unroll
            for (int mi = 0; mi < 2; mi++)
#pragma unroll
                for (int ni = 0; ni < 2; ni++) {
                    wmma::mma_sync(acc[mi][ni], ah[mi], bh[ni], acc[mi][ni]);
                    wmma::mma_sync(acc[mi][ni], ah[mi], bl[ni], acc[mi][ni]);
                    wmma::mma_sync(acc[mi][ni], al[mi], bh[ni], acc[mi][ni]);
                }
        }
    }
    __syncthreads();
#pragma unroll
    for (int mi = 0; mi < 2; mi++)
#pragma unroll
        for (int ni = 0; ni < 2; ni++)
            wmma::store_matrix_sync(Cs + (m0 + mi * 16) * B_LDC + nw0 + ni * 16,
                                    acc[mi][ni], B_LDC, wmma::mem_row_major);
    __syncthreads();
#pragma unroll
    for (int i = 0; i < 32; i++) {
        int idx = tid + i * 256;
        int d = idx & 63, c = idx >> 6;
        atomicAdd(&g_KVT[((size_t)b * NC + cblk * 128 + c) * ND + d], Cs[c * B_LDC + d]);
    }
}

// ---------------------------------------------------------------------------
// kD: D[p][c] = sum_d qf[p][d]*KVT[c][d]
//     out = x + (gamma/S[p])*D + gamma*bv[c]   (bias folded analytically)
// ---------------------------------------------------------------------------
#define D_KS   0
#define D_NORM 256
#define D_AH   768
#define D_AL   (768 + 18432)
#define D_BH   (768 + 36864)
#define D_BL   (768 + 46080)
#define D_CS   (768 + 55296)
#define D_TOT  (768 + 55296 + 34816)
#define D_LD   72
#define D_LDC  68

__global__ void __launch_bounds__(256) kD_out(
    const float* __restrict__ x, const float* __restrict__ gamma,
    const float* __restrict__ bv, float* __restrict__ out)
{
    extern __shared__ char smem[];
    float* s_ks = (float*)(smem + D_KS);
    float* s_nm = (float*)(smem + D_NORM);
    __nv_bfloat16* As_hi = (__nv_bfloat16*)(smem + D_AH);
    __nv_bfloat16* As_lo = (__nv_bfloat16*)(smem + D_AL);
    __nv_bfloat16* Bs_hi = (__nv_bfloat16*)(smem + D_BH);
    __nv_bfloat16* Bs_lo = (__nv_bfloat16*)(smem + D_BL);
    float* Cs = (float*)(smem + D_CS);

    const int tid = threadIdx.x, wid = tid >> 5;
    const int b = blockIdx.y, n0 = blockIdx.x * 128;
    const float gam = gamma[0];

    if (tid < 64) s_ks[tid] = g_Ksum[b * 64 + tid] + EPSF;

#pragma unroll
    for (int i = 0; i < 8; i++) {
        int idx = tid + i * 256;
        int q4 = idx & 15, row = idx >> 4;
        size_t base = ((size_t)b * NN + n0 + row) * ND + q4 * 4;
        uint2 vh = *reinterpret_cast<const uint2*>(g_qf_hi + base);
        uint2 vl = *reinterpret_cast<const uint2*>(g_qf_lo + base);
        *reinterpret_cast<uint2*>(&As_hi[row * D_LD + q4 * 4]) = vh;
        *reinterpret_cast<uint2*>(&As_lo[row * D_LD + q4 * 4]) = vl;
    }
    __syncthreads();

    if (tid < 128) {
        float s = 0.0f;
#pragma unroll
        for (int dp = 0; dp < 32; dp++) {
            __nv_bfloat162 hh = *reinterpret_cast<__nv_bfloat162*>(&As_hi[tid * D_LD + dp * 2]);
            __nv_bfloat162 ll = *reinterpret_cast<__nv_bfloat162*>(&As_lo[tid * D_LD + dp * 2]);
            float f0 = __bfloat162float(__low2bfloat16(hh)) + __bfloat162float(__low2bfloat16(ll));
            float f1 = __bfloat162float(__high2bfloat16(hh)) + __bfloat162float(__high2bfloat16(ll));
            s += f0 * s_ks[dp * 2] + f1 * s_ks[dp * 2 + 1];
        }
        s_nm[tid] = gam / s;
    }

    const int m0 = (wid & 3) * 32;
    const int nw0 = (wid >> 2) * 32;

    for (int cc = 0; cc < 8; cc++) {
        const int c0 = cc * 64;
        __syncthreads();
#pragma unroll
        for (int i = 0; i < 8; i++) {
            int idx = tid + i * 256;
            int dp = idx & 31, row = idx >> 5;
            const float2 v = *reinterpret_cast<const float2*>(
                g_KVT + ((size_t)b * NC + c0 + row) * ND + dp * 2);
            __nv_bfloat16 h0, l0, h1, l1;
            split_bf16(v.x, h0, l0); split_bf16(v.y, h1, l1);
            *reinterpret_cast<__nv_bfloat162*>(&Bs_hi[row * D_LD + dp * 2]) = __halves2bfloat162(h0, h1);
            *reinterpret_cast<__nv_bfloat162*>(&Bs_lo[row * D_LD + dp * 2]) = __halves2bfloat162(l0, l1);
        }
        __syncthreads();

        FragC acc[2][2];
#pragma unroll
        for (int mi = 0; mi < 2; mi++)
#pragma unroll
            for (int ni = 0; ni < 2; ni++) wmma::fill_fragment(acc[mi][ni], 0.0f);

#pragma unroll
        for (int s = 0; s < 4; s++) {
            FragAr ah[2], al[2];
            FragBc bh[2], bl[2];
#pragma unroll
            for (int mi = 0; mi < 2; mi++) {
                wmma::load_matrix_sync(ah[mi], As_hi + (m0 + mi * 16) * D_LD + s * 16, D_LD);
                wmma::load_matrix_sync(al[mi], As_lo + (m0 + mi * 16) * D_LD + s * 16, D_LD);
            }
#pragma unroll
            for (int ni = 0; ni < 2; ni++) {
                wmma::load_matrix_sync(bh[ni], Bs_hi + (nw0 + ni * 16) * D_LD + s * 16, D_LD);
                wmma::load_matrix_sync(bl[ni], Bs_lo + (nw0 + ni * 16) * D_LD + s * 16, D_LD);
            }
#pragma unroll
            for (int mi = 0; mi < 2; mi++)
#pragma unroll
                for (int ni = 0; ni < 2; ni++) {
                    wmma::mma_sync(acc[mi][ni], ah[mi], bh[ni], acc[mi][ni]);
                    wmma::mma_sync(acc[mi][ni], ah[mi], bl[ni], acc[mi][ni]);
                    wmma::mma_sync(acc[mi][ni], al[mi], bh[ni], acc[mi][ni]);
                }
        }
#pragma unroll
        for (int mi = 0; mi < 2; mi++)
#pragma unroll
            for (int ni = 0; ni < 2; ni++)
                wmma::store_matrix_sync(Cs + (m0 + mi * 16) * D_LDC + nw0 + ni * 16,
                                        acc[mi][ni], D_LDC, wmma::mem_row_major);
        __syncthreads();
#pragma unroll
        for (int i = 0; i < 32; i++) {
            int idx = tid + i * 256;
            int p = idx & 127, c = idx >> 7;   // c warp-uniform
            float gbv = gam * bv[c0 + c];
            size_t off = ((size_t)b * NC + c0 + c) * NN + n0 + p;
            out[off] = x[off] + s_nm[p] * Cs[p * D_LDC + c] + gbv;
        }
    }
}

// ---------------------------------------------------------------------------
extern "C" void kernel_launch(void* const* d_in, const int* in_sizes, int n_in,
                              void* d_out, int out_size)
{
    (void)in_sizes; (void)n_in; (void)out_size;
    const float* x     = (const float*)d_in[0];
    const float* wq    = (const float*)d_in[1];
    const float* bq    = (const float*)d_in[2];
    const float* wk    = (const float*)d_in[3];
    const float* bk    = (const float*)d_in[4];
    const float* wv    = (const float*)d_in[5];
    const float* bv    = (const float*)d_in[6];
    const float* gamma = (const float*)d_in[7];
    float* out = (float*)d_out;

    cudaFuncSetAttribute(kA_proj, cudaFuncAttributeMaxDynamicSharedMemorySize, A_TOT);
    cudaFuncSetAttribute(kB_kx,   cudaFuncAttributeMaxDynamicSharedMemorySize, B_TOT);
    cudaFuncSetAttribute(k2_kv,   cudaFuncAttributeMaxDynamicSharedMemorySize, B_TOT);
    cudaFuncSetAttribute(kD_out,  cudaFuncAttributeMaxDynamicSharedMemorySize, D_TOT);

    k_zero<<<256, 256>>>();
    kA_proj<<<dim3(NN / 128, NB), 256, A_TOT>>>(x, wq, bq, wk, bk);
    kB_kx<<<dim3(4, NB, 4), 256, B_TOT>>>(x);
    k2_kv<<<dim3(4, NB, 4), 256, B_TOT>>>(wv);
    kD_out<<<dim3(NN / 128, NB), 256, D_TOT>>>(x, gamma, bv, out);
}